// round 1
// baseline (speedup 1.0000x reference)
#include <cuda_runtime.h>
#include <math.h>

#define NB      512
#define DEMB    512
#define T       1042
#define TP      1056
#define TPQ     (TP/4)
#define KE      6400
#define KT      528
#define M_EMB   8192
#define M_PAIR  65536
#define M_REL   4096

// ---------------- scratch (device globals; no allocation) ----------------
__device__ float g_tagged[(size_t)M_EMB * KT];    // emb(512) + tags(9) + pad -> 528
__device__ float g_P[(size_t)M_EMB * TP];         // tagged @ Wg1_top
__device__ float g_Q[(size_t)M_EMB * TP];         // tagged @ Wg1_bot
__device__ float g_H1[(size_t)M_PAIR * TP];       // pair layer activations (reused for G3)
__device__ float g_H2[(size_t)M_PAIR * TP];
__device__ float g_R[(size_t)M_EMB * TP];         // per-(b,k) sums over j
__device__ float g_rel[(size_t)M_REL * TP];       // relations (B*8 rows)
__device__ float g_Hf[(size_t)M_REL * TP];
__device__ float g_fo[M_REL];
__device__ float g_W1t[(size_t)KT * TP];
__device__ float g_W1b[(size_t)KT * TP];
__device__ float g_W2[(size_t)TP * TP];
__device__ float g_W3[(size_t)TP * TP];
__device__ float g_Wf1[(size_t)TP * TP];
__device__ float g_Wf2p[TP];
__device__ float g_b1[TP];
__device__ float g_b2[TP];
__device__ float g_b3[TP];
__device__ float g_bf1[TP];

// ---------------- generic padded copy: dst[dR x dC] <- src (zero pad) ----
__global__ void pad2d_k(float* __restrict__ dst, const float* __restrict__ src,
                        int dR, int dC, int sR, int sC, int sStride, int sRowOff)
{
    int idx = blockIdx.x * blockDim.x + threadIdx.x;
    if (idx >= dR * dC) return;
    int r = idx / dC, c = idx % dC;
    float v = 0.f;
    if (r < sR && c < sC) v = src[(size_t)(r + sRowOff) * sStride + c];
    dst[idx] = v;
}

// ---------------- tag one-hot fill into tagged cols [512,528) -------------
__global__ void tagfill_k(float* __restrict__ tg)
{
    int idx = blockIdx.x * blockDim.x + threadIdx.x;   // M_EMB * 16
    if (idx >= M_EMB * 16) return;
    int r = idx >> 4, c = idx & 15;
    int p = r & 15;
    int t = (p < 8) ? p : 8;
    tg[(size_t)r * KT + 512 + c] = (c == t) ? 1.f : 0.f;
}

// ---------------- SGEMM: C = A(MxK) * B(KxN) [+bias][+relu] --------------
// Requires: M % 128 == 0, K % 8 == 0, N % 4 == 0. N edge handled by guards.
template<int EPI>   // 0 = none, 1 = +bias, 2 = +bias,relu
__global__ void __launch_bounds__(256, 2) sgemm_k(
    const float* __restrict__ A, int lda,
    const float* __restrict__ B, int ldb,
    float* __restrict__ C, int ldc,
    int M, int N, int K, const float* __restrict__ bias)
{
    constexpr int BM = 128, BN = 128, BK = 8;
    __shared__ float As[BK][BM];
    __shared__ float Bs[BK][BN];

    const int tid = threadIdx.x;
    const int tx = tid & 15;          // 0..15  (N micro)
    const int ty = tid >> 4;          // 0..15  (M micro)

    const int arow = tid >> 1;                    // 0..127
    const int akk  = (tid & 1) * 4;               // 0 or 4
    const int brow = tid >> 5;                    // 0..7 (k)
    const int bcol_loc = (tid & 31) * 4;          // 0..124
    const int bcol = blockIdx.x * BN + bcol_loc;
    const bool bValid = (bcol < N);

    const float* Ap = A + (size_t)(blockIdx.y * BM + arow) * lda + akk;
    const float* Bp = B + (size_t)brow * ldb + bcol;

    float acc[8][8];
    #pragma unroll
    for (int i = 0; i < 8; i++)
        #pragma unroll
        for (int j = 0; j < 8; j++) acc[i][j] = 0.f;

    for (int k0 = 0; k0 < K; k0 += BK) {
        float4 a4 = *reinterpret_cast<const float4*>(Ap);
        Ap += BK;
        float4 b4 = make_float4(0.f, 0.f, 0.f, 0.f);
        if (bValid) b4 = *reinterpret_cast<const float4*>(Bp);
        Bp += (size_t)BK * ldb;

        As[akk + 0][arow] = a4.x;
        As[akk + 1][arow] = a4.y;
        As[akk + 2][arow] = a4.z;
        As[akk + 3][arow] = a4.w;
        *reinterpret_cast<float4*>(&Bs[brow][bcol_loc]) = b4;
        __syncthreads();

        #pragma unroll
        for (int kk = 0; kk < BK; kk++) {
            float a[8], b[8];
            *reinterpret_cast<float4*>(&a[0]) = *reinterpret_cast<const float4*>(&As[kk][ty * 8]);
            *reinterpret_cast<float4*>(&a[4]) = *reinterpret_cast<const float4*>(&As[kk][ty * 8 + 4]);
            *reinterpret_cast<float4*>(&b[0]) = *reinterpret_cast<const float4*>(&Bs[kk][tx * 8]);
            *reinterpret_cast<float4*>(&b[4]) = *reinterpret_cast<const float4*>(&Bs[kk][tx * 8 + 4]);
            #pragma unroll
            for (int i = 0; i < 8; i++)
                #pragma unroll
                for (int j = 0; j < 8; j++)
                    acc[i][j] += a[i] * b[j];
        }
        __syncthreads();
    }

    // epilogue (vectorized, N % 4 == 0)
    #pragma unroll
    for (int i = 0; i < 8; i++) {
        const int row = blockIdx.y * BM + ty * 8 + i;
        #pragma unroll
        for (int j = 0; j < 8; j += 4) {
            const int col = blockIdx.x * BN + tx * 8 + j;
            if (col < N) {
                float4 v = make_float4(acc[i][j], acc[i][j+1], acc[i][j+2], acc[i][j+3]);
                if (EPI >= 1) {
                    float4 bb = *reinterpret_cast<const float4*>(&bias[col]);
                    v.x += bb.x; v.y += bb.y; v.z += bb.z; v.w += bb.w;
                }
                if (EPI == 2) {
                    v.x = fmaxf(v.x, 0.f); v.y = fmaxf(v.y, 0.f);
                    v.z = fmaxf(v.z, 0.f); v.w = fmaxf(v.w, 0.f);
                }
                *reinterpret_cast<float4*>(&C[(size_t)row * ldc + col]) = v;
            }
        }
    }
}

// ---------------- H1 expand: relu(P[b,j] + Q[b,k] + bg1) ------------------
__global__ void expand_h1_k(const float* __restrict__ P, const float* __restrict__ Q,
                            const float* __restrict__ b1, float* __restrict__ H1)
{
    int idx = blockIdx.x * blockDim.x + threadIdx.x;   // M_PAIR * TPQ
    if (idx >= M_PAIR * TPQ) return;
    int c4 = idx % TPQ;
    int r  = idx / TPQ;
    int b = r >> 7;
    int k = (r >> 3) & 15;
    int j = r & 7;
    float4 p = reinterpret_cast<const float4*>(P)[(size_t)(b * 16 + j) * TPQ + c4];
    float4 q = reinterpret_cast<const float4*>(Q)[(size_t)(b * 16 + k) * TPQ + c4];
    float4 bb = reinterpret_cast<const float4*>(b1)[c4];
    float4 o;
    o.x = fmaxf(p.x + q.x + bb.x, 0.f);
    o.y = fmaxf(p.y + q.y + bb.y, 0.f);
    o.z = fmaxf(p.z + q.z + bb.z, 0.f);
    o.w = fmaxf(p.w + q.w + bb.w, 0.f);
    reinterpret_cast<float4*>(H1)[(size_t)idx] = o;
}

// ---------------- sum over groups of 8 consecutive rows -------------------
__global__ void reduce8_k(const float* __restrict__ G, float* __restrict__ R)
{
    int idx = blockIdx.x * blockDim.x + threadIdx.x;   // M_EMB * TPQ
    if (idx >= M_EMB * TPQ) return;
    int c4 = idx % TPQ;
    int m  = idx / TPQ;
    const float4* g = reinterpret_cast<const float4*>(G) + (size_t)(m * 8) * TPQ + c4;
    float4 s = make_float4(0.f, 0.f, 0.f, 0.f);
    #pragma unroll
    for (int j = 0; j < 8; j++) {
        float4 v = g[(size_t)j * TPQ];
        s.x += v.x; s.y += v.y; s.z += v.z; s.w += v.w;
    }
    reinterpret_cast<float4*>(R)[(size_t)idx] = s;
}

// --------- relations[b,a] = sum_{k<8} R[b,k] + R[b,8+a] -------------------
__global__ void relations_k(const float* __restrict__ R, float* __restrict__ rel)
{
    int idx = blockIdx.x * blockDim.x + threadIdx.x;   // NB * TPQ
    if (idx >= NB * TPQ) return;
    int c4 = idx % TPQ;
    int b  = idx / TPQ;
    const float4* r = reinterpret_cast<const float4*>(R) + (size_t)(b * 16) * TPQ + c4;
    float4 cs = make_float4(0.f, 0.f, 0.f, 0.f);
    #pragma unroll
    for (int k = 0; k < 8; k++) {
        float4 v = r[(size_t)k * TPQ];
        cs.x += v.x; cs.y += v.y; cs.z += v.z; cs.w += v.w;
    }
    #pragma unroll
    for (int a = 0; a < 8; a++) {
        float4 v = r[(size_t)(8 + a) * TPQ];
        float4 o = make_float4(cs.x + v.x, cs.y + v.y, cs.z + v.z, cs.w + v.w);
        reinterpret_cast<float4*>(rel)[(size_t)(b * 8 + a) * TPQ + c4] = o;
    }
}

__inline__ __device__ float warp_sum(float v)
{
    #pragma unroll
    for (int o = 16; o; o >>= 1) v += __shfl_down_sync(0xffffffffu, v, o);
    return v;
}

// ---------------- f_out[row] = Hf[row,:] . Wf2 + bf2 ----------------------
__global__ void fout_k(const float* __restrict__ Hf, const float* __restrict__ W,
                       const float* __restrict__ bf2, float* __restrict__ fo)
{
    int row = blockIdx.x;
    const float* h = Hf + (size_t)row * TP;
    float s = 0.f;
    for (int c = threadIdx.x; c < TP; c += 128) s += h[c] * W[c];
    s = warp_sum(s);
    __shared__ float sh[4];
    if ((threadIdx.x & 31) == 0) sh[threadIdx.x >> 5] = s;
    __syncthreads();
    if (threadIdx.x == 0) fo[row] = sh[0] + sh[1] + sh[2] + sh[3] + bf2[0];
}

// ---------------- loss + acc ---------------------------------------------
__global__ void loss_k(const float* __restrict__ fo, const int* __restrict__ labels,
                       float* __restrict__ out)
{
    int b = threadIdx.x;   // 512 threads
    int lab = labels[b];
    float lsum = 0.f;
    float best = -1e30f; int bi = 0;
    #pragma unroll
    for (int a = 0; a < 8; a++) {
        float f = fo[b * 8 + a];
        float l = fmaxf(f, 0.f) - f * ((a == lab) ? 1.f : 0.f) + log1pf(expf(-fabsf(f)));
        lsum += l;
        if (f > best) { best = f; bi = a; }
    }
    float cor = (bi == lab) ? 1.f : 0.f;

    lsum = warp_sum(lsum);
    cor  = warp_sum(cor);
    __shared__ float sl[16], sc[16];
    int wid = threadIdx.x >> 5, lane = threadIdx.x & 31;
    if (lane == 0) { sl[wid] = lsum; sc[wid] = cor; }
    __syncthreads();
    if (wid == 0) {
        float a = (lane < 16) ? sl[lane] : 0.f;
        float c = (lane < 16) ? sc[lane] : 0.f;
        a = warp_sum(a);
        c = warp_sum(c);
        if (lane == 0) {
            out[0] = a / (float)(NB * 8);
            out[1] = c / (float)NB;
        }
    }
}

// ---------------- host ----------------------------------------------------
static inline int cdiv(int a, int b) { return (a + b - 1) / b; }

extern "C" void kernel_launch(void* const* d_in, const int* in_sizes, int n_in,
                              void* d_out, int out_size)
{
    const float* x      = (const float*)d_in[0];
    const float* W_emb  = (const float*)d_in[1];
    const float* b_emb  = (const float*)d_in[2];
    const float* Wg1    = (const float*)d_in[3];
    const float* bg1    = (const float*)d_in[4];
    const float* Wg2    = (const float*)d_in[5];
    const float* bg2    = (const float*)d_in[6];
    const float* Wg3    = (const float*)d_in[7];
    const float* bg3    = (const float*)d_in[8];
    const float* Wf1    = (const float*)d_in[9];
    const float* bf1    = (const float*)d_in[10];
    const float* Wf2    = (const float*)d_in[11];
    const float* bf2    = (const float*)d_in[12];
    const int*   labels = (const int*)d_in[13];
    float* out = (float*)d_out;

    float *tagged, *P, *Q, *H1, *H2, *R, *rel, *Hf, *fo;
    float *W1t, *W1b, *W2p, *W3p, *Wf1p, *Wf2p, *b1p, *b2p, *b3p, *bf1p;
    cudaGetSymbolAddress((void**)&tagged, g_tagged);
    cudaGetSymbolAddress((void**)&P, g_P);
    cudaGetSymbolAddress((void**)&Q, g_Q);
    cudaGetSymbolAddress((void**)&H1, g_H1);
    cudaGetSymbolAddress((void**)&H2, g_H2);
    cudaGetSymbolAddress((void**)&R, g_R);
    cudaGetSymbolAddress((void**)&rel, g_rel);
    cudaGetSymbolAddress((void**)&Hf, g_Hf);
    cudaGetSymbolAddress((void**)&fo, g_fo);
    cudaGetSymbolAddress((void**)&W1t, g_W1t);
    cudaGetSymbolAddress((void**)&W1b, g_W1b);
    cudaGetSymbolAddress((void**)&W2p, g_W2);
    cudaGetSymbolAddress((void**)&W3p, g_W3);
    cudaGetSymbolAddress((void**)&Wf1p, g_Wf1);
    cudaGetSymbolAddress((void**)&Wf2p, g_Wf2p);
    cudaGetSymbolAddress((void**)&b1p, g_b1);
    cudaGetSymbolAddress((void**)&b2p, g_b2);
    cudaGetSymbolAddress((void**)&b3p, g_b3);
    cudaGetSymbolAddress((void**)&bf1p, g_bf1);

    // --- weight/bias padding + tag construction ---
    pad2d_k<<<cdiv(KT * TP, 256), 256>>>(W1t, Wg1, KT, TP, 521, T, T, 0);
    pad2d_k<<<cdiv(KT * TP, 256), 256>>>(W1b, Wg1, KT, TP, 521, T, T, 521);
    pad2d_k<<<cdiv(TP * TP, 256), 256>>>(W2p, Wg2, TP, TP, T, T, T, 0);
    pad2d_k<<<cdiv(TP * TP, 256), 256>>>(W3p, Wg3, TP, TP, T, T, T, 0);
    pad2d_k<<<cdiv(TP * TP, 256), 256>>>(Wf1p, Wf1, TP, TP, T, T, T, 0);
    pad2d_k<<<cdiv(TP, 256), 256>>>(Wf2p, Wf2, 1, TP, 1, T, T, 0);
    pad2d_k<<<cdiv(TP, 256), 256>>>(b1p, bg1, 1, TP, 1, T, T, 0);
    pad2d_k<<<cdiv(TP, 256), 256>>>(b2p, bg2, 1, TP, 1, T, T, 0);
    pad2d_k<<<cdiv(TP, 256), 256>>>(b3p, bg3, 1, TP, 1, T, T, 0);
    pad2d_k<<<cdiv(TP, 256), 256>>>(bf1p, bf1, 1, TP, 1, T, T, 0);
    tagfill_k<<<cdiv(M_EMB * 16, 256), 256>>>(tagged);

    dim3 blk(256);
    // emb = x @ W_emb + b_emb  -> tagged[:, 0:512]  (ldc = 528)
    sgemm_k<1><<<dim3(4, M_EMB / 128), blk>>>(x, KE, W_emb, DEMB, tagged, KT, M_EMB, DEMB, KE, b_emb);
    // P = tagged @ Wg1_top ; Q = tagged @ Wg1_bot  (no bias/relu yet)
    sgemm_k<0><<<dim3(9, M_EMB / 128), blk>>>(tagged, KT, W1t, TP, P, TP, M_EMB, TP, KT, nullptr);
    sgemm_k<0><<<dim3(9, M_EMB / 128), blk>>>(tagged, KT, W1b, TP, Q, TP, M_EMB, TP, KT, nullptr);
    // H1[b,k,j] = relu(P[b,j] + Q[b,k] + bg1)
    expand_h1_k<<<cdiv(M_PAIR * TPQ, 256), 256>>>(P, Q, b1p, H1);
    // H2 = relu(H1 @ Wg2 + bg2) ; G3 = relu(H2 @ Wg3 + bg3) (reuses H1)
    sgemm_k<2><<<dim3(9, M_PAIR / 128), blk>>>(H1, TP, W2p, TP, H2, TP, M_PAIR, TP, TP, b2p);
    sgemm_k<2><<<dim3(9, M_PAIR / 128), blk>>>(H2, TP, W3p, TP, H1, TP, M_PAIR, TP, TP, b3p);
    // R[b,k] = sum_j G3[b,k,j] ; relations[b,a] = sum_{k<8} R[b,k] + R[b,8+a]
    reduce8_k<<<cdiv(M_EMB * TPQ, 256), 256>>>(H1, R);
    relations_k<<<cdiv(NB * TPQ, 256), 256>>>(R, rel);
    // Hf = relu(rel @ Wf1 + bf1) ; f_out = Hf . Wf2 + bf2
    sgemm_k<2><<<dim3(9, M_REL / 128), blk>>>(rel, TP, Wf1p, TP, Hf, TP, M_REL, TP, TP, bf1p);
    fout_k<<<M_REL, 128>>>(Hf, Wf2p, bf2, fo);
    loss_k<<<1, 512>>>(fo, labels, out);
}

// round 3
// speedup vs baseline: 1.2249x; 1.2249x over previous
#include <cuda_runtime.h>
#include <cstdint>
#include <math.h>

#define NBATCH  512
#define T       1042
#define TP      1056
#define TPQ     (TP/4)
#define KE      6400
#define KT      544
#define M_EMB   8192
#define M_PAIR  65536
#define M_REL   4096

// ---------------- scratch (device globals; no allocation) ----------------
__device__ float g_tagged[(size_t)M_EMB * KT];
__device__ float g_P[(size_t)M_EMB * TP];
__device__ float g_Q[(size_t)M_EMB * TP];
__device__ float g_H2[(size_t)M_PAIR * TP];
__device__ float g_R[(size_t)M_EMB * TP];
__device__ float g_rel[(size_t)M_REL * TP];
__device__ float g_Hf[(size_t)M_REL * TP];
__device__ float g_fo[M_REL];
__device__ float g_WembT[(size_t)512 * KE];
__device__ float g_W1tT[(size_t)TP * KT];
__device__ float g_W1bT[(size_t)TP * KT];
__device__ float g_W2T[(size_t)TP * TP];
__device__ float g_W3T[(size_t)TP * TP];
__device__ float g_Wf1T[(size_t)TP * TP];
__device__ float g_Wf2p[TP];
__device__ float g_b1[TP];
__device__ float g_b2[TP];
__device__ float g_b3[TP];
__device__ float g_bf1[TP];

// ---------------- helpers -------------------------------------------------
__device__ __forceinline__ float tf32r(float a) {
    uint32_t r;
    asm("cvt.rna.tf32.f32 %0, %1;" : "=r"(r) : "f"(a));
    return __uint_as_float(r);
}
__device__ __forceinline__ void mma8(float acc[4], const uint32_t a[4], const uint32_t b[2]) {
    asm volatile(
        "mma.sync.aligned.m16n8k8.row.col.f32.tf32.tf32.f32 "
        "{%0,%1,%2,%3},{%4,%5,%6,%7},{%8,%9},{%0,%1,%2,%3};"
        : "+f"(acc[0]), "+f"(acc[1]), "+f"(acc[2]), "+f"(acc[3])
        : "r"(a[0]), "r"(a[1]), "r"(a[2]), "r"(a[3]), "r"(b[0]), "r"(b[1]));
}

// ================= 3xTF32 mma.sync GEMM ===================================
// C[M x N] = A[M x K] @ Bt[N x K]^T.  BM=BN=128, BK=16, 256 threads.
// Warp grid 2(m) x 4(n); warp tile 64x32; frags m16n8k8.
// EPI: 0 none, 1 +bias, 2 +bias+relu, 3 +bias+relu+sum over groups of 8 rows.
// AFUSE: A row computed as relu(A[p-row] + A2[q-row] + Ab) on the fly.
//
// Smem stage layout (floats): Ahi[2*PA] | Alo[2*PA] | Bhi[2*PB] | Blo[2*PB]
// A perm: [kstep][rb 0..7][lane][4]  (lane = r*4+c, regs a0..a3 of the frag)
// B perm: [kstep][nb 0..15][lane][2]
// PA/PB padded so kstep stride != 0 mod 32 banks.
template<int EPI, int AFUSE>
__global__ void __launch_bounds__(256, 1) mmagemm_k(
    const float* __restrict__ A, int lda,
    const float* __restrict__ A2, const float* __restrict__ Ab,
    const float* __restrict__ B, int ldb, int Ncols,
    float* __restrict__ C, int ldc,
    int K, const float* __restrict__ bias)
{
    extern __shared__ float smf[];
    constexpr int PA = 1028, PB = 1060;
    constexpr int A_LO = 2 * PA;              // 2056
    constexpr int B_HI = 4 * PA;              // 4112
    constexpr int B_LO = B_HI + 2 * PB;       // 6232
    constexpr int STG  = B_HI + 4 * PB;       // 8352 floats per stage

    const int t  = threadIdx.x;
    const int m0 = blockIdx.y * 128, n0 = blockIdx.x * 128;

    // ---- producer addressing ----
    const int prow = t >> 1, pks = t & 1;
    const int pr = prow & 7, prbit = (prow >> 3) & 1, prb = prow >> 4, pnb = prow >> 3;
    const float *ApA, *ApQ = nullptr;
    if (AFUSE) {
        int gr = m0 + prow;
        int bb = gr >> 7, kk = (gr >> 3) & 15, jj = gr & 7;
        ApA = A  + (size_t)(bb * 16 + jj) * lda + pks * 8;
        ApQ = A2 + (size_t)(bb * 16 + kk) * lda + pks * 8;
    } else {
        ApA = A + (size_t)(m0 + prow) * lda + pks * 8;
    }
    const float* Bpp = B + (size_t)(n0 + prow) * ldb + pks * 8;
    const bool bval = (n0 + prow) < Ncols;

    float va[8], vb[8];

    // ---- consumer addressing ----
    const int L = t & 31, wid = t >> 5, wm = wid >> 2, wn = wid & 3;
    float acc[4][4][4];
    #pragma unroll
    for (int i = 0; i < 4; i++)
        #pragma unroll
        for (int j = 0; j < 4; j++)
            #pragma unroll
            for (int v = 0; v < 4; v++) acc[i][j][v] = 0.f;

    const int KB = K >> 4;

    // ---------- load tile (registers) ----------
    auto ldtile = [&](int k0) {
        if (AFUSE) {
            float4 p0 = *(const float4*)(ApA + k0);
            float4 p1 = *(const float4*)(ApA + k0 + 4);
            float4 q0 = *(const float4*)(ApQ + k0);
            float4 q1 = *(const float4*)(ApQ + k0 + 4);
            float4 c0 = *(const float4*)(Ab + k0 + pks * 8);
            float4 c1 = *(const float4*)(Ab + k0 + pks * 8 + 4);
            va[0] = fmaxf(p0.x + q0.x + c0.x, 0.f);
            va[1] = fmaxf(p0.y + q0.y + c0.y, 0.f);
            va[2] = fmaxf(p0.z + q0.z + c0.z, 0.f);
            va[3] = fmaxf(p0.w + q0.w + c0.w, 0.f);
            va[4] = fmaxf(p1.x + q1.x + c1.x, 0.f);
            va[5] = fmaxf(p1.y + q1.y + c1.y, 0.f);
            va[6] = fmaxf(p1.z + q1.z + c1.z, 0.f);
            va[7] = fmaxf(p1.w + q1.w + c1.w, 0.f);
        } else {
            float4 x0 = *(const float4*)(ApA + k0);
            float4 x1 = *(const float4*)(ApA + k0 + 4);
            va[0] = x0.x; va[1] = x0.y; va[2] = x0.z; va[3] = x0.w;
            va[4] = x1.x; va[5] = x1.y; va[6] = x1.z; va[7] = x1.w;
        }
        float4 y0 = make_float4(0.f, 0.f, 0.f, 0.f);
        float4 y1 = make_float4(0.f, 0.f, 0.f, 0.f);
        if (bval) {
            y0 = *(const float4*)(Bpp + k0);
            y1 = *(const float4*)(Bpp + k0 + 4);
        }
        vb[0] = y0.x; vb[1] = y0.y; vb[2] = y0.z; vb[3] = y0.w;
        vb[4] = y1.x; vb[5] = y1.y; vb[6] = y1.z; vb[7] = y1.w;
    };

    // ---------- split + store tile to smem (fragment-permuted) ----------
    auto sttile = [&](float* stg) {
        float* ad = stg + pks * PA + prb * 128;
        float* bd = stg + B_HI + pks * PB + pnb * 66;
        #pragma unroll
        for (int j = 0; j < 8; j++) {
            float v = va[j];
            float h = tf32r(v), l = tf32r(v - h);
            int ai = (pr * 4 + (j & 3)) * 4 + (j >> 2) * 2 + prbit;
            ad[ai] = h;
            ad[A_LO + ai] = l;
            float w  = vb[j];
            float hh = tf32r(w), ll = tf32r(w - hh);
            int bi = (pr * 4 + (j & 3)) * 2 + (j >> 2);
            bd[bi] = hh;
            bd[(B_LO - B_HI) + bi] = ll;
        }
    };

    // ---------- consume one stage ----------
    auto consume = [&](const float* stg) {
        #pragma unroll
        for (int ks = 0; ks < 2; ks++) {
            uint32_t ah[4][4], al[4][4], bh[4][2], bl[4][2];
            const float* ab = stg + ks * PA + wm * 512 + L * 4;
            #pragma unroll
            for (int mf = 0; mf < 4; mf++) {
                *(uint4*)ah[mf] = *(const uint4*)(ab + mf * 128);
                *(uint4*)al[mf] = *(const uint4*)(ab + A_LO + mf * 128);
            }
            const float* bb = stg + B_HI + ks * PB + wn * 264 + L * 2;
            #pragma unroll
            for (int nf = 0; nf < 4; nf++) {
                *(uint2*)bh[nf] = *(const uint2*)(bb + nf * 66);
                *(uint2*)bl[nf] = *(const uint2*)(bb + (B_LO - B_HI) + nf * 66);
            }
            #pragma unroll
            for (int mf = 0; mf < 4; mf++)
                #pragma unroll
                for (int nf = 0; nf < 4; nf++) {
                    mma8(acc[mf][nf], ah[mf], bh[nf]);
                    mma8(acc[mf][nf], ah[mf], bl[nf]);
                    mma8(acc[mf][nf], al[mf], bh[nf]);
                }
        }
    };

    // ---------- pipelined main loop ----------
    ldtile(0);
    sttile(smf);
    __syncthreads();
    for (int kb = 0; kb < KB; kb++) {
        if (kb + 1 < KB) ldtile((kb + 1) * 16);
        consume(smf + (kb & 1) * STG);
        if (kb + 1 < KB) sttile(smf + ((kb + 1) & 1) * STG);
        __syncthreads();
    }

    // ---------- epilogue ----------
    const int baseRow  = m0 + wm * 64;
    const int colBase  = n0 + wn * 32 + (L & 3) * 2;
    #pragma unroll
    for (int mf = 0; mf < 4; mf++) {
        #pragma unroll
        for (int nf = 0; nf < 4; nf++) {
            int col = colBase + nf * 8;
            bool cv = col < Ncols;
            float c0 = acc[mf][nf][0], c1 = acc[mf][nf][1];
            float c2 = acc[mf][nf][2], c3 = acc[mf][nf][3];
            if (EPI >= 1) {
                float2 b2 = cv ? *(const float2*)(bias + col) : make_float2(0.f, 0.f);
                c0 += b2.x; c1 += b2.y; c2 += b2.x; c3 += b2.y;
            }
            if (EPI >= 2) {
                c0 = fmaxf(c0, 0.f); c1 = fmaxf(c1, 0.f);
                c2 = fmaxf(c2, 0.f); c3 = fmaxf(c3, 0.f);
            }
            if (EPI == 3) {
                c0 += __shfl_down_sync(0xffffffffu, c0, 16);
                c0 += __shfl_down_sync(0xffffffffu, c0, 8);
                c0 += __shfl_down_sync(0xffffffffu, c0, 4);
                c1 += __shfl_down_sync(0xffffffffu, c1, 16);
                c1 += __shfl_down_sync(0xffffffffu, c1, 8);
                c1 += __shfl_down_sync(0xffffffffu, c1, 4);
                c2 += __shfl_down_sync(0xffffffffu, c2, 16);
                c2 += __shfl_down_sync(0xffffffffu, c2, 8);
                c2 += __shfl_down_sync(0xffffffffu, c2, 4);
                c3 += __shfl_down_sync(0xffffffffu, c3, 16);
                c3 += __shfl_down_sync(0xffffffffu, c3, 8);
                c3 += __shfl_down_sync(0xffffffffu, c3, 4);
                if (L < 4 && cv) {
                    int g = (baseRow + mf * 16) >> 3;
                    *(float2*)(C + (size_t)g * ldc + col)       = make_float2(c0, c1);
                    *(float2*)(C + (size_t)(g + 1) * ldc + col) = make_float2(c2, c3);
                }
            } else {
                if (cv) {
                    int row = baseRow + mf * 16 + (L >> 2);
                    *(float2*)(C + (size_t)row * ldc + col)       = make_float2(c0, c1);
                    *(float2*)(C + (size_t)(row + 8) * ldc + col) = make_float2(c2, c3);
                }
            }
        }
    }
}

// ======================= small kernels ====================================
__global__ void pad2d_k(float* __restrict__ dst, const float* __restrict__ src,
                        int dR, int dC, int sR, int sC, int sStride, int sRowOff)
{
    int idx = blockIdx.x * blockDim.x + threadIdx.x;
    if (idx >= dR * dC) return;
    int r = idx / dC, c = idx % dC;
    float v = 0.f;
    if (r < sR && c < sC) v = src[(size_t)(r + sRowOff) * sStride + c];
    dst[idx] = v;
}

// dst[r, c] = src[(c + rowOff) * sStride + r]  (zero-padded), dst is [DR x DC]
__global__ void transposeT_k(float* __restrict__ dst, const float* __restrict__ src,
                             int DR, int DC, int sR, int sC, int sStride, int rowOff)
{
    __shared__ float tbuf[32][33];
    int c0 = blockIdx.x * 32;
    int r0 = blockIdx.y * 32;
    int tx = threadIdx.x, ty = threadIdx.y;
    #pragma unroll
    for (int i = ty; i < 32; i += 8) {
        int srow = c0 + i, scol = r0 + tx;
        tbuf[i][tx] = (srow < sR && scol < sC) ? src[(size_t)(srow + rowOff) * sStride + scol] : 0.f;
    }
    __syncthreads();
    #pragma unroll
    for (int i = ty; i < 32; i += 8) {
        int r = r0 + i, c = c0 + tx;
        if (r < DR && c < DC) dst[(size_t)r * DC + c] = tbuf[tx][i];
    }
}

__global__ void tagfill_k(float* __restrict__ tg)
{
    int idx = blockIdx.x * blockDim.x + threadIdx.x;   // M_EMB * 32
    if (idx >= M_EMB * 32) return;
    int r = idx >> 5, c = idx & 31;
    int p = r & 15;
    int tt = (p < 8) ? p : 8;
    tg[(size_t)r * KT + 512 + c] = (c == tt) ? 1.f : 0.f;
}

__global__ void relations_k(const float* __restrict__ R, float* __restrict__ rel)
{
    int idx = blockIdx.x * blockDim.x + threadIdx.x;   // NBATCH * TPQ
    if (idx >= NBATCH * TPQ) return;
    int c4 = idx % TPQ;
    int b  = idx / TPQ;
    const float4* r = reinterpret_cast<const float4*>(R) + (size_t)(b * 16) * TPQ + c4;
    float4 cs = make_float4(0.f, 0.f, 0.f, 0.f);
    #pragma unroll
    for (int k = 0; k < 8; k++) {
        float4 v = r[(size_t)k * TPQ];
        cs.x += v.x; cs.y += v.y; cs.z += v.z; cs.w += v.w;
    }
    #pragma unroll
    for (int a = 0; a < 8; a++) {
        float4 v = r[(size_t)(8 + a) * TPQ];
        float4 o = make_float4(cs.x + v.x, cs.y + v.y, cs.z + v.z, cs.w + v.w);
        reinterpret_cast<float4*>(rel)[(size_t)(b * 8 + a) * TPQ + c4] = o;
    }
}

__inline__ __device__ float warp_sum(float v)
{
    #pragma unroll
    for (int o = 16; o; o >>= 1) v += __shfl_down_sync(0xffffffffu, v, o);
    return v;
}

__global__ void fout_k(const float* __restrict__ Hf, const float* __restrict__ W,
                       const float* __restrict__ bf2, float* __restrict__ fo)
{
    int row = blockIdx.x;
    const float* h = Hf + (size_t)row * TP;
    float s = 0.f;
    for (int c = threadIdx.x; c < TP; c += 128) s += h[c] * W[c];
    s = warp_sum(s);
    __shared__ float sh[4];
    if ((threadIdx.x & 31) == 0) sh[threadIdx.x >> 5] = s;
    __syncthreads();
    if (threadIdx.x == 0) fo[row] = sh[0] + sh[1] + sh[2] + sh[3] + bf2[0];
}

__global__ void loss_k(const float* __restrict__ fo, const int* __restrict__ labels,
                       float* __restrict__ out)
{
    int b = threadIdx.x;   // 512 threads
    int lab = labels[b];
    float lsum = 0.f;
    float best = -1e30f; int bi = 0;
    #pragma unroll
    for (int a = 0; a < 8; a++) {
        float f = fo[b * 8 + a];
        float l = fmaxf(f, 0.f) - f * ((a == lab) ? 1.f : 0.f) + log1pf(expf(-fabsf(f)));
        lsum += l;
        if (f > best) { best = f; bi = a; }
    }
    float cor = (bi == lab) ? 1.f : 0.f;
    lsum = warp_sum(lsum);
    cor  = warp_sum(cor);
    __shared__ float sl[16], sc[16];
    int wid = threadIdx.x >> 5, lane = threadIdx.x & 31;
    if (lane == 0) { sl[wid] = lsum; sc[wid] = cor; }
    __syncthreads();
    if (wid == 0) {
        float a = (lane < 16) ? sl[lane] : 0.f;
        float c = (lane < 16) ? sc[lane] : 0.f;
        a = warp_sum(a);
        c = warp_sum(c);
        if (lane == 0) {
            out[0] = a / (float)(NBATCH * 8);
            out[1] = c / (float)NBATCH;
        }
    }
}

// ======================= host =============================================
static inline int cdiv(int a, int b) { return (a + b - 1) / b; }

extern "C" void kernel_launch(void* const* d_in, const int* in_sizes, int n_in,
                              void* d_out, int out_size)
{
    const float* x      = (const float*)d_in[0];
    const float* W_emb  = (const float*)d_in[1];
    const float* b_emb  = (const float*)d_in[2];
    const float* Wg1    = (const float*)d_in[3];
    const float* bg1    = (const float*)d_in[4];
    const float* Wg2    = (const float*)d_in[5];
    const float* bg2    = (const float*)d_in[6];
    const float* Wg3    = (const float*)d_in[7];
    const float* bg3    = (const float*)d_in[8];
    const float* Wf1    = (const float*)d_in[9];
    const float* bf1    = (const float*)d_in[10];
    const float* Wf2    = (const float*)d_in[11];
    const float* bf2    = (const float*)d_in[12];
    const int*   labels = (const int*)d_in[13];
    float* out = (float*)d_out;

    float *tagged, *P, *Q, *H2, *R, *rel, *Hf, *fo;
    float *WembT, *W1tT, *W1bT, *W2T, *W3T, *Wf1T, *Wf2p, *b1p, *b2p, *b3p, *bf1p;
    cudaGetSymbolAddress((void**)&tagged, g_tagged);
    cudaGetSymbolAddress((void**)&P, g_P);
    cudaGetSymbolAddress((void**)&Q, g_Q);
    cudaGetSymbolAddress((void**)&H2, g_H2);
    cudaGetSymbolAddress((void**)&R, g_R);
    cudaGetSymbolAddress((void**)&rel, g_rel);
    cudaGetSymbolAddress((void**)&Hf, g_Hf);
    cudaGetSymbolAddress((void**)&fo, g_fo);
    cudaGetSymbolAddress((void**)&WembT, g_WembT);
    cudaGetSymbolAddress((void**)&W1tT, g_W1tT);
    cudaGetSymbolAddress((void**)&W1bT, g_W1bT);
    cudaGetSymbolAddress((void**)&W2T, g_W2T);
    cudaGetSymbolAddress((void**)&W3T, g_W3T);
    cudaGetSymbolAddress((void**)&Wf1T, g_Wf1T);
    cudaGetSymbolAddress((void**)&Wf2p, g_Wf2p);
    cudaGetSymbolAddress((void**)&b1p, g_b1);
    cudaGetSymbolAddress((void**)&b2p, g_b2);
    cudaGetSymbolAddress((void**)&b3p, g_b3);
    cudaGetSymbolAddress((void**)&bf1p, g_bf1);

    const int SMB = 2 * 8352 * 4;   // 66816 bytes dynamic smem
    cudaFuncSetAttribute(mmagemm_k<1,0>, cudaFuncAttributeMaxDynamicSharedMemorySize, SMB);
    cudaFuncSetAttribute(mmagemm_k<0,0>, cudaFuncAttributeMaxDynamicSharedMemorySize, SMB);
    cudaFuncSetAttribute(mmagemm_k<2,1>, cudaFuncAttributeMaxDynamicSharedMemorySize, SMB);
    cudaFuncSetAttribute(mmagemm_k<3,0>, cudaFuncAttributeMaxDynamicSharedMemorySize, SMB);
    cudaFuncSetAttribute(mmagemm_k<2,0>, cudaFuncAttributeMaxDynamicSharedMemorySize, SMB);

    dim3 tb(32, 8);
    // Transposed / padded weights: Bt[n, k] = W[k, n]
    transposeT_k<<<dim3(200, 16), tb>>>(WembT, W_emb, 512, KE, KE, 512, 512, 0);
    transposeT_k<<<dim3(17, 33), tb>>>(W1tT, Wg1, TP, KT, 521, T, T, 0);
    transposeT_k<<<dim3(17, 33), tb>>>(W1bT, Wg1, TP, KT, 521, T, T, 521);
    transposeT_k<<<dim3(33, 33), tb>>>(W2T,  Wg2, TP, TP, T, T, T, 0);
    transposeT_k<<<dim3(33, 33), tb>>>(W3T,  Wg3, TP, TP, T, T, T, 0);
    transposeT_k<<<dim3(33, 33), tb>>>(Wf1T, Wf1, TP, TP, T, T, T, 0);
    pad2d_k<<<cdiv(TP, 256), 256>>>(Wf2p, Wf2, 1, TP, 1, T, T, 0);
    pad2d_k<<<cdiv(TP, 256), 256>>>(b1p, bg1, 1, TP, 1, T, T, 0);
    pad2d_k<<<cdiv(TP, 256), 256>>>(b2p, bg2, 1, TP, 1, T, T, 0);
    pad2d_k<<<cdiv(TP, 256), 256>>>(b3p, bg3, 1, TP, 1, T, T, 0);
    pad2d_k<<<cdiv(TP, 256), 256>>>(bf1p, bf1, 1, TP, 1, T, T, 0);
    tagfill_k<<<cdiv(M_EMB * 32, 256), 256>>>(tagged);

    // emb = x @ W_emb + b_emb -> tagged[:, 0:512]  (ldc = 544)
    mmagemm_k<1,0><<<dim3(4, M_EMB/128), 256, SMB>>>(
        x, KE, nullptr, nullptr, WembT, KE, 512, tagged, KT, KE, b_emb);
    // P = tagged @ Wg1_top ; Q = tagged @ Wg1_bot
    mmagemm_k<0,0><<<dim3(9, M_EMB/128), 256, SMB>>>(
        tagged, KT, nullptr, nullptr, W1tT, KT, TP, P, TP, KT, nullptr);
    mmagemm_k<0,0><<<dim3(9, M_EMB/128), 256, SMB>>>(
        tagged, KT, nullptr, nullptr, W1bT, KT, TP, Q, TP, KT, nullptr);
    // H2 = relu(relu(P[j]+Q[k]+b1) @ Wg2 + b2)  (H1 expand fused into A producer)
    mmagemm_k<2,1><<<dim3(9, M_PAIR/128), 256, SMB>>>(
        P, TP, Q, b1p, W2T, TP, TP, H2, TP, TP, b2p);
    // R[b,k] = sum_j relu(H2 @ Wg3 + b3)  (8-row reduction fused in epilogue)
    mmagemm_k<3,0><<<dim3(9, M_PAIR/128), 256, SMB>>>(
        H2, TP, nullptr, nullptr, W3T, TP, TP, R, TP, TP, b3p);
    // relations
    relations_k<<<cdiv(NBATCH * TPQ, 256), 256>>>(R, rel);
    // Hf = relu(rel @ Wf1 + bf1)
    mmagemm_k<2,0><<<dim3(9, M_REL/128), 256, SMB>>>(
        rel, TP, nullptr, nullptr, Wf1T, TP, TP, Hf, TP, TP, bf1p);
    fout_k<<<M_REL, 128>>>(Hf, Wf2p, bf2, fo);
    loss_k<<<1, 512>>>(fo, labels, out);
}